// round 11
// baseline (speedup 1.0000x reference)
#include <cuda_runtime.h>

#define BB 4
#define EE 1500
#define DD 256
#define HH 8
#define DK 32

#define O_ATTN 1536000
#define O_APE  73536000
#define D8_LD 1504

typedef unsigned long long ull;

// ---------------- scratch (no allocation allowed) ----------------
__device__ float g_q[BB*HH*EE*DK];            // scaled q, [b,h,e,dk]
__device__ ulonglong2 g_k2[BB*HH*12*1024];    // K pair-transposed, chunk-major: [bh][c][j][64] ull2
__device__ ull g_v2[BB*HH*12*64*32];          // V pair-major, chunk-major: [bh][c][kp][d] ull={k even,k odd}
__device__ float g_qdr[BB*HH*EE*8];           // q . base_rpr[p], p padded to 8
__device__ float g_o[BB*EE*DD];               // attention output pre-FC, [b,e,h*32+d]
__device__ float g_asum[BB*EE];
__device__ int   g_acnt[BB*EE];
__device__ unsigned char g_d8[BB*EE*D8_LD];   // dist compressed: 0..3 valid, 255 masked

__device__ __forceinline__ float warp_sum(float v) {
    #pragma unroll
    for (int o = 16; o; o >>= 1) v += __shfl_xor_sync(0xffffffffu, v, o);
    return v;
}

// packed f32x2 helpers (sm_100+)
__device__ __forceinline__ void fma2(ull &d, ull a, ull b) {
    asm("fma.rn.f32x2 %0, %1, %2, %0;" : "+l"(d) : "l"(a), "l"(b));
}
__device__ __forceinline__ float f2sum(ull u) {
    float lo, hi;
    asm("mov.b64 {%0,%1}, %2;" : "=f"(lo), "=f"(hi) : "l"(u));
    return lo + hi;
}
__device__ __forceinline__ ull packf2(float x, float y) {
    ull u;
    asm("mov.b64 %0, {%1,%2};" : "=l"(u) : "f"(x), "f"(y));
    return u;
}

// ---------------- mbarrier + bulk-copy helpers ----------------
__device__ __forceinline__ void mbar_init(unsigned a, unsigned cnt) {
    asm volatile("mbarrier.init.shared.b64 [%0], %1;" :: "r"(a), "r"(cnt) : "memory");
}
__device__ __forceinline__ void mbar_arrive(unsigned a) {
    asm volatile("mbarrier.arrive.shared.b64 _, [%0];" :: "r"(a) : "memory");
}
__device__ __forceinline__ void mbar_expect_tx(unsigned a, unsigned bytes) {
    asm volatile("mbarrier.arrive.expect_tx.shared.b64 _, [%0], %1;"
                 :: "r"(a), "r"(bytes) : "memory");
}
__device__ __forceinline__ void bulk_g2s(unsigned dst, const void* src, unsigned bytes, unsigned mbar) {
    asm volatile("cp.async.bulk.shared::cta.global.mbarrier::complete_tx::bytes [%0], [%1], %2, [%3];"
                 :: "r"(dst), "l"(src), "r"(bytes), "r"(mbar) : "memory");
}
#define MBAR_WAIT(addr, par) do { \
    asm volatile( \
        "{\n\t.reg .pred P;\n\t" \
        "WL%=:\n\t" \
        "mbarrier.try_wait.parity.acquire.cta.shared::cta.b64 P, [%0], %1, 0x989680;\n\t" \
        "@P bra WD%=;\n\t" \
        "bra WL%=;\n\t" \
        "WD%=:\n\t}" \
        :: "r"(addr), "r"(par) : "memory"); \
} while (0)

#define GROUP_BAR(gid) \
    asm volatile("bar.sync %0, 256;" :: "r"((gid) + 1) : "memory")

// ---------------- K0: zero accumulators ----------------
__global__ void zero_kernel() {
    int i = blockIdx.x * 256 + threadIdx.x;
    if (i < BB*EE) { g_asum[i] = 0.f; g_acnt[i] = 0; }
}

// ---------------- K0a: zero V2 tail pad (chunk 11, kp 46..63) ----------------
__global__ void zerov2_kernel() {
    int i = blockIdx.x * 256 + threadIdx.x;   // 32*18*32 = 18432
    if (i < 18432) {
        int bh = i / 576;
        int rem = i % 576;
        int kp = 46 + rem / 32;
        int d = rem % 32;
        g_v2[(((long long)bh*12 + 11)*64 + kp)*32 + d] = 0ull;
    }
}

// ---------------- K0b: valid counts + d8 compression ----------------
__global__ void __launch_bounds__(256) countwrite_kernel(const int* __restrict__ dist) {
    int b  = blockIdx.y;
    int q0 = blockIdx.x * 8;
    int t  = threadIdx.x;
    const int* dpb = dist + (long long)b*EE*EE;
    unsigned char* d8 = g_d8 + (long long)b*EE*D8_LD;
    for (int k = t; k < EE; k += 256) {
        int cnt = 0;
        #pragma unroll
        for (int r = 0; r < 8; r++) {
            int q = q0 + r;
            if (q < EE) {
                int dv = dpb[(long long)q*EE + k];
                bool ok = (dv <= 3);
                d8[q*D8_LD + k] = ok ? (unsigned char)dv : (unsigned char)255;
                cnt += ok ? 1 : 0;
            }
        }
        atomicAdd(&g_acnt[b*EE + k], cnt);
    }
}

// ---------------- K1: layernorm + QKV projections + q.rpr + K/V pair layouts ----------------
__global__ void __launch_bounds__(256) proj_kernel(
    const float* __restrict__ x,
    const float* __restrict__ Wq, const float* __restrict__ Wk,
    const float* __restrict__ Wv,
    const float* __restrict__ lnw, const float* __restrict__ lnb,
    const float* __restrict__ rpr)
{
    __shared__ __align__(16) float ssm[256*8];   // [d][r] raw input rows -> later K transpose buffer
    __shared__ __align__(16) float nsm[256*8];   // [d][r] layernormed rows
    int b  = blockIdx.y;
    int e0 = blockIdx.x * 8;
    int t  = threadIdx.x;
    const float* xb = x + b*(DD*EE);

    for (int i = t; i < 2048; i += 256) {
        int d = i >> 3, r = i & 7;
        int e = e0 + r;
        ssm[i] = (e < EE) ? xb[d*EE + e] : 0.f;
    }
    __syncthreads();

    int w = t >> 5, lane = t & 31;
    {   // layernorm of row w (one row per warp)
        float s = 0.f;
        #pragma unroll
        for (int i = 0; i < 8; i++) s += ssm[(lane + 32*i)*8 + w];
        s = warp_sum(s);
        float mu = s * (1.f/256.f);
        float vs = 0.f;
        #pragma unroll
        for (int i = 0; i < 8; i++) {
            float dlt = ssm[(lane + 32*i)*8 + w] - mu;
            vs += dlt*dlt;
        }
        vs = warp_sum(vs);
        float rstd = rsqrtf(vs * (1.f/256.f) + 1e-6f);
        #pragma unroll
        for (int i = 0; i < 8; i++) {
            int d = lane + 32*i;
            nsm[d*8 + w] = (ssm[d*8 + w] - mu) * rstd * lnw[d] + lnb[d];
        }
    }
    __syncthreads();

    int j = t;
    float aq[8], ak[8], av[8];
    #pragma unroll
    for (int r = 0; r < 8; r++) { aq[r] = 0.f; ak[r] = 0.f; av[r] = 0.f; }

    #pragma unroll 4
    for (int d = 0; d < 256; d++) {
        float wq = Wq[d*256 + j];
        float wk = Wk[d*256 + j];
        float wv = Wv[d*256 + j];
        float4 s0 = *(const float4*)&ssm[d*8];
        float4 s1 = *(const float4*)&ssm[d*8 + 4];
        float4 n0 = *(const float4*)&nsm[d*8];
        float4 n1 = *(const float4*)&nsm[d*8 + 4];
        aq[0] += n0.x*wq; aq[1] += n0.y*wq; aq[2] += n0.z*wq; aq[3] += n0.w*wq;
        aq[4] += n1.x*wq; aq[5] += n1.y*wq; aq[6] += n1.z*wq; aq[7] += n1.w*wq;
        ak[0] += s0.x*wk; ak[1] += s0.y*wk; ak[2] += s0.z*wk; ak[3] += s0.w*wk;
        ak[4] += s1.x*wk; ak[5] += s1.y*wk; ak[6] += s1.z*wk; ak[7] += s1.w*wk;
        av[0] += s0.x*wv; av[1] += s0.y*wv; av[2] += s0.z*wv; av[3] += s0.w*wv;
        av[4] += s1.x*wv; av[5] += s1.y*wv; av[6] += s1.z*wv; av[7] += s1.w*wv;
    }

    int h = j >> 5, dk = j & 31;
    const float inv_sqrt_dk = 0.17677669529663687f;  // 1/sqrt(32)
    float qsv[8];
    #pragma unroll
    for (int r = 0; r < 8; r++) qsv[r] = aq[r] * inv_sqrt_dk;

    #pragma unroll
    for (int r = 0; r < 8; r++) {
        int e = e0 + r;
        if (e < EE)
            g_q[((b*HH + h)*EE + e)*32 + dk] = qsv[r];
    }

    // V pair-major: ull = {V[2kp][d], V[2kp+1][d]}, chunk-major
    {
        int kp0 = e0 >> 1;            // multiple of 4, never crosses 64-boundary within 4
        int cc = kp0 >> 6, kpl = kp0 & 63;
        long long vb = (((long long)(b*HH + h)*12 + cc)*64 + kpl)*32 + dk;
        #pragma unroll
        for (int i = 0; i < 4; i++) {
            int e = e0 + 2*i;
            if (e + 1 < EE)
                g_v2[vb + i*32] = packf2(av[2*i], av[2*i + 1]);
        }
    }

    #pragma unroll
    for (int p = 0; p < 6; p++) {
        float rv = rpr[p*32 + lane];
        #pragma unroll
        for (int r = 0; r < 8; r++) {
            float pv = warp_sum(qsv[r] * rv);
            if (lane == 0 && (e0 + r) < EE)
                g_qdr[((b*HH + h)*EE + (e0 + r))*8 + p] = pv;
        }
    }

    // ---- K pair-transpose into chunk-major g_k2[bh][c][j][64] ----
    __syncthreads();                     // all ssm/nsm reads done
    #pragma unroll
    for (int r = 0; r < 8; r++) ssm[t*8 + r] = ak[r];   // ssm[(h*32+dk)][r]
    __syncthreads();
    {
        int hh = t >> 5;                 // 0..7
        int jj = (t >> 1) & 15;          // 0..15 d-pair
        int ph = t & 1;                  // which half of the 4 pairs
        const float* s0 = &ssm[(hh*32 + 2*jj    )*8];
        const float* s1 = &ssm[(hh*32 + 2*jj + 1)*8];
        int pg = e0 >> 1;                // first pair (multiple of 4)
        int cc = pg >> 6, pl = pg & 63;
        long long base = (((long long)(b*HH + hh)*12 + cc)*16 + jj)*64 + pl + 2*ph;
        #pragma unroll
        for (int ps = 0; ps < 2; ps++) {
            int ee = 4*ph + 2*ps;        // local e of k=2p
            ulonglong2 val;
            val.x = packf2(s0[ee],   s1[ee]);
            val.y = packf2(s0[ee+1], s1[ee+1]);
            g_k2[base + ps] = val;
        }
    }
}

// ---------------- K2: attention (768 threads, 3 groups x 8 rows, shared staging) ----------------
#define SC_LD 1512
// floats: mbar 16 + sc 24*1512 + 3 bufs (3*4096) + qsm 768 + qdr 192 + flaginv 24 + invr 24 + part 3*2112
#define SMEM_ATTN ((16 + 24*SC_LD + 3*4096 + 768 + 192 + 24 + 24 + 3*2112)*4)
#define CHUNK_BYTES 16384u

__global__ void __launch_bounds__(768, 1) attn_kernel(float* __restrict__ out)
{
    extern __shared__ __align__(16) float sm[];
    float* sc      = sm + 16;                // 24 x 1512 (group g owns rows [8g, 8g+8))
    float* bufs    = sc + 24*SC_LD;          // 3 x 4096 floats (shared staging)
    float* qsm     = bufs + 3*4096;          // 24 x 32 scaled q
    float* qdr     = qsm + 768;              // 24 x 8 bias table
    float* flaginv = qdr + 192;              // 24
    float* invr    = flaginv + 24;           // 24
    float* part    = invr + 24;              // 3 x 8 x 264 floats

    int qt = blockIdx.x, h = blockIdx.y, b = blockIdx.z;
    int q0 = qt * 24;
    int t  = threadIdx.x;
    int g  = t >> 8;          // group 0..2
    int gt = t & 255;         // thread within group
    int w8 = gt >> 5;         // warp within group 0..7
    int lane = t & 31;
    int bh = b*HH + h;

    float* scg      = sc + g*8*SC_LD;
    float* qsmg     = qsm + g*256;
    float* qdrg     = qdr + g*64;
    float* flaginvg = flaginv + g*8;
    float* invrg    = invr + g*8;
    float* partg    = part + g*2112;

    unsigned smb = (unsigned)__cvta_generic_to_shared(sm);
    unsigned mbF0 = smb, mbF1 = smb + 8, mbF2 = smb + 16;
    unsigned mbE0 = smb + 24, mbE1 = smb + 32, mbE2 = smb + 40;
    unsigned bsm[3] = {
        (unsigned)__cvta_generic_to_shared(bufs),
        (unsigned)__cvta_generic_to_shared(bufs + 4096),
        (unsigned)__cvta_generic_to_shared(bufs + 8192)
    };

    const ulonglong2* k2base = g_k2 + (long long)bh*12*1024;
    const ull* v2base = g_v2 + (long long)bh*12*2048;
    const unsigned char* d8b = g_d8 + (long long)b*EE*D8_LD;

    // -------- prologue --------
    {
        int row = t >> 5;                // 0..23
        int qg = q0 + row;
        qsm[t] = (qg < EE) ? g_q[(bh*EE + qg)*32 + lane] : 0.f;
    }
    if (t < 192) {
        int qg = q0 + (t >> 3);
        qdr[t] = (qg < EE) ? g_qdr[(bh*EE + qg)*8 + (t & 7)] : 0.f;
    }
    if (t < 288) {   // zero sc pad cols 1500..1511 (AV tail safety)
        sc[(t/12)*SC_LD + 1500 + (t%12)] = 0.f;
    }
    if (t == 0) {
        mbar_init(mbF0, 1); mbar_init(mbF1, 1); mbar_init(mbF2, 1);
        mbar_init(mbE0, 768); mbar_init(mbE1, 768); mbar_init(mbE2, 768);
        mbar_expect_tx(mbF0, CHUNK_BYTES); bulk_g2s(bsm[0], k2base,        CHUNK_BYTES, mbF0);
        mbar_expect_tx(mbF1, CHUNK_BYTES); bulk_g2s(bsm[1], k2base + 1024, CHUNK_BYTES, mbF1);
        mbar_expect_tx(mbF2, CHUNK_BYTES); bulk_g2s(bsm[2], k2base + 2048, CHUNK_BYTES, mbF2);
    }
    __syncthreads();

    unsigned mbF[3] = {mbF0, mbF1, mbF2};
    unsigned mbE[3] = {mbE0, mbE1, mbE2};

    // ================= score phase =================
    // warp w8 owns pairs [w8*8, +8); lane: qq = (gt>>3)&3, kl = gt&7
    // thread: rows {qq (regs), qq+4 (smem)} x pair p0i (k = 2p, 2p+1)
    int qq = (gt >> 3) & 3;
    int p0i = w8*8 + (gt & 7);
    int qg0 = q0 + g*8 + qq, qg1 = qg0 + 4;

    ull qr0[16];
    {
        const ull* a = (const ull*)(qsmg + qq*32);
        #pragma unroll
        for (int jj = 0; jj < 16; jj++) qr0[jj] = a[jj];
    }
    const ull* q1p = (const ull*)(qsmg + (qq + 4)*32);

    uchar2 dA, dB;
    {
        int kgA = 2*p0i;
        dA = (qg0 < EE) ? *(const uchar2*)(d8b + (long long)qg0*D8_LD + kgA) : make_uchar2(255, 255);
        dB = (qg1 < EE) ? *(const uchar2*)(d8b + (long long)qg1*D8_LD + kgA) : make_uchar2(255, 255);
    }

    for (int c = 0; c < 12; c++) {
        int kc = c * 128;
        int bi = c % 3, par = (c/3) & 1;

        uchar2 eA = make_uchar2(255, 255), eB = make_uchar2(255, 255);
        if (c < 11) {
            int kg2 = kc + 128 + 2*p0i;
            if (kg2 < EE) {
                if (qg0 < EE) eA = *(const uchar2*)(d8b + (long long)qg0*D8_LD + kg2);
                if (qg1 < EE) eB = *(const uchar2*)(d8b + (long long)qg1*D8_LD + kg2);
            }
        }

        MBAR_WAIT(mbF[bi], par);

        const ulonglong2* prow = (const ulonglong2*)(bufs + bi*4096) + p0i;
        ull a00 = 0, a01 = 0, a10 = 0, a11 = 0;
        #pragma unroll
        for (int jj = 0; jj < 16; jj++) {
            ulonglong2 kv = prow[jj*64];
            ull q1j = q1p[jj];
            fma2(a00, qr0[jj], kv.x); fma2(a01, qr0[jj], kv.y);
            fma2(a10, q1j,     kv.x); fma2(a11, q1j,     kv.y);
        }

        int kgA = kc + 2*p0i;
        if (kgA < EE) {
            float sa = -1e9f, sb = -1e9f;
            if (dA.x <= 3) sa = f2sum(a00) + qdrg[qq*8 + dA.x];
            if (dA.y <= 3) sb = f2sum(a01) + qdrg[qq*8 + dA.y];
            *(ull*)&scg[qq*SC_LD + kgA] = packf2(sa, sb);
            sa = -1e9f; sb = -1e9f;
            if (dB.x <= 3) sa = f2sum(a10) + qdrg[(qq + 4)*8 + dB.x];
            if (dB.y <= 3) sb = f2sum(a11) + qdrg[(qq + 4)*8 + dB.y];
            *(ull*)&scg[(qq + 4)*SC_LD + kgA] = packf2(sa, sb);
        }

        mbar_arrive(mbE[bi]);            // done reading buf bi for chunk c
        if (t == 0 && c < 9) {           // stage K chunk c+3 into buf bi
            MBAR_WAIT(mbE[bi], par);
            mbar_expect_tx(mbF[bi], CHUNK_BYTES);
            bulk_g2s(bsm[bi], k2base + (c + 3)*1024, CHUNK_BYTES, mbF[bi]);
        }
        dA = eA; dB = eB;
    }

    // V chunks 0..2 (producer waits last K reads of each buffer)
    if (t == 736) {
        #pragma unroll
        for (int i = 0; i < 3; i++) {
            MBAR_WAIT(mbE[i], 1);        // K uses 9+i done (4th completion pending -> parity 1)
            mbar_expect_tx(mbF[i], CHUNK_BYTES);
            bulk_g2s(bsm[i], v2base + i*2048, CHUNK_BYTES, mbF[i]);
        }
    }

    GROUP_BAR(g);   // group's score stores visible

    // ===== softmax (one row per warp), 2-pass =====
    {
        int rr = w8;
        int qg = q0 + g*8 + rr;
        if (qg < EE) {
            float* row = scg + rr*SC_LD;
            float sum = 0.f;
            for (int k = lane*4; k < EE; k += 128) {
                float4 v = *(float4*)&row[k];
                v.x = __expf(v.x); v.y = __expf(v.y);
                v.z = __expf(v.z); v.w = __expf(v.w);
                *(float4*)&row[k] = v;
                sum += (v.x + v.y) + (v.z + v.w);
            }
            sum = warp_sum(sum);
            bool fullmask = (sum == 0.f);
            if (fullmask) {
                for (int k = lane*4; k < EE; k += 128)
                    *(float4*)&row[k] = make_float4(1.f, 1.f, 1.f, 1.f);
                sum = (float)EE;
            }
            float inv = 1.f / sum;
            if (lane == 0) {
                invrg[rr] = inv;
                flaginvg[rr] = fullmask ? 0.f : inv;
            }
            long long obase = (long long)O_ATTN + (long long)(bh*EE + qg)*EE;
            for (int k = lane*4; k < EE; k += 128) {
                float4 v = *(const float4*)&row[k];
                v.x *= inv; v.y *= inv; v.z *= inv; v.w *= inv;
                *(float4*)&out[obase + k] = v;
            }
        } else {
            if (lane == 0) { invrg[rr] = 0.f; flaginvg[rr] = 0.f; }
        }
    }
    GROUP_BAR(g);

    // column sums over this group's 8 rows
    for (int k = gt; k < EE; k += 256) {
        float s = 0.f;
        #pragma unroll
        for (int r = 0; r < 8; r++) s += scg[r*SC_LD + k] * flaginvg[r];
        atomicAdd(&g_asum[b*EE + k], s);
    }

    // ================= AV =================
    // warp w8 = k-slice (8 kp per chunk), lane = d; thread owns all 8 group rows.
    ull acc[8];
    #pragma unroll
    for (int r = 0; r < 8; r++) acc[r] = 0;

    for (int c = 0; c < 12; c++) {
        int bi = c % 3, par = (c/3) & 1;
        MBAR_WAIT(mbF[bi], par);

        bool live = !(c == 11 && w8 >= 6);   // kp >= 48 of chunk 11 all invalid
        if (live) {
            const ull* vb = (const ull*)(bufs + bi*4096) + (w8*8)*32 + lane;
            ull v0 = vb[0],    v1 = vb[32],  v2 = vb[64],  v3 = vb[96];
            ull v4 = vb[128],  v5 = vb[160], v6 = vb[192], v7 = vb[224];
            #pragma unroll
            for (int r = 0; r < 8; r++) {
                const ulonglong2* ar = (const ulonglong2*)scg + r*378 + c*32 + w8*4;
                ulonglong2 A0 = ar[0], A1 = ar[1], A2 = ar[2], A3 = ar[3];
                fma2(acc[r], A0.x, v0); fma2(acc[r], A0.y, v1);
                fma2(acc[r], A1.x, v2); fma2(acc[r], A1.y, v3);
                fma2(acc[r], A2.x, v4); fma2(acc[r], A2.y, v5);
                fma2(acc[r], A3.x, v6); fma2(acc[r], A3.y, v7);
            }
        }

        mbar_arrive(mbE[bi]);
        if (t == 736 && c < 9) {
            MBAR_WAIT(mbE[bi], par);
            mbar_expect_tx(mbF[bi], CHUNK_BYTES);
            bulk_g2s(bsm[bi], v2base + (c + 3)*2048, CHUNK_BYTES, mbF[bi]);
        }
    }

    // per-warp k-slice partials -> smem -> cross-warp reduce
    #pragma unroll
    for (int r = 0; r < 8; r++)
        partg[w8*264 + r*33 + lane] = f2sum(acc[r]);
    GROUP_BAR(g);
    {
        int rr = gt >> 5, dd = gt & 31;
        float s = 0.f;
        #pragma unroll
        for (int ww = 0; ww < 8; ww++) s += partg[ww*264 + rr*33 + dd];
        int qg = q0 + g*8 + rr;
        if (qg < EE)
            g_o[(b*EE + qg)*DD + h*32 + dd] = s * invrg[rr];
    }
}

// ---------------- K3: FC + residual + transpose-out ----------------
__global__ void __launch_bounds__(256) fc_kernel(
    const float* __restrict__ x, const float* __restrict__ Wfc,
    float* __restrict__ out)
{
    __shared__ __align__(16) float osm[256*8];   // [d][r]
    int b  = blockIdx.y;
    int e0 = blockIdx.x * 8;
    int t  = threadIdx.x;

    for (int i = t; i < 2048; i += 256) {
        int r = i >> 8, d = i & 255;
        int e = e0 + r;
        osm[d*8 + r] = (e < EE) ? g_o[(b*EE + e)*DD + d] : 0.f;
    }
    __syncthreads();

    int j = t;
    const float* xb = x + b*DD*EE + j*EE;
    float acc[8];
    #pragma unroll
    for (int r = 0; r < 8; r++) {
        int e = e0 + r;
        acc[r] = (e < EE) ? xb[e] : 0.f;   // residual
    }
    #pragma unroll 4
    for (int d = 0; d < 256; d++) {
        float wv = Wfc[d*256 + j];
        float4 o0 = *(const float4*)&osm[d*8];
        float4 o1 = *(const float4*)&osm[d*8 + 4];
        acc[0] += o0.x*wv; acc[1] += o0.y*wv; acc[2] += o0.z*wv; acc[3] += o0.w*wv;
        acc[4] += o1.x*wv; acc[5] += o1.y*wv; acc[6] += o1.z*wv; acc[7] += o1.w*wv;
    }
    float* ob = out + b*DD*EE + j*EE + e0;
    if (e0 + 8 <= EE) {
        *(float4*)ob       = make_float4(acc[0], acc[1], acc[2], acc[3]);
        *(float4*)(ob + 4) = make_float4(acc[4], acc[5], acc[6], acc[7]);
    } else {
        for (int r = 0; r < 8; r++)
            if (e0 + r < EE) ob[r] = acc[r];
    }
}

// ---------------- K4: attn_per_edge ----------------
__global__ void finalize_kernel(float* __restrict__ out) {
    int i = blockIdx.x * 256 + threadIdx.x;
    if (i < BB*EE) {
        out[O_APE + i] = g_asum[i] / (float)g_acnt[i];
    }
}

// ---------------- launch ----------------
extern "C" void kernel_launch(void* const* d_in, const int* in_sizes, int n_in,
                              void* d_out, int out_size)
{
    const float* x    = (const float*)d_in[0];
    const int*   dist = (const int*)  d_in[1];
    const float* Wq   = (const float*)d_in[2];
    const float* Wk   = (const float*)d_in[3];
    const float* Wv   = (const float*)d_in[4];
    const float* Wfc  = (const float*)d_in[5];
    const float* lnw  = (const float*)d_in[6];
    const float* lnb  = (const float*)d_in[7];
    const float* rpr  = (const float*)d_in[8];
    float* out = (float*)d_out;

    cudaFuncSetAttribute(attn_kernel,
        cudaFuncAttributeMaxDynamicSharedMemorySize, SMEM_ATTN);

    zero_kernel<<<24, 256>>>();
    zerov2_kernel<<<72, 256>>>();

    dim3 gc(188, BB);
    countwrite_kernel<<<gc, 256>>>(dist);

    dim3 g1(188, BB);
    proj_kernel<<<g1, 256>>>(x, Wq, Wk, Wv, lnw, lnb, rpr);

    dim3 g2(63, HH, BB);
    attn_kernel<<<g2, 768, SMEM_ATTN>>>(out);

    dim3 g3(188, BB);
    fc_kernel<<<g3, 256>>>(x, Wfc, out);

    finalize_kernel<<<24, 256>>>(out);
}

// round 12
// speedup vs baseline: 1.0855x; 1.0855x over previous
#include <cuda_runtime.h>

#define BB 4
#define EE 1500
#define DD 256
#define HH 8
#define DK 32

#define O_ATTN 1536000
#define O_APE  73536000
#define D8_LD 1504

typedef unsigned long long ull;

// ---------------- scratch (no allocation allowed) ----------------
__device__ float g_q[BB*HH*EE*DK];              // scaled q, [b,h,e,dk]
__device__ ulonglong2 g_k2[BB*HH*24*512];       // K pair-transposed, 24 chunks: [bh][c][j16][p32]
__device__ float g_v[BB*HH*1536*DK];            // V natural [k][d], padded to 1536 rows
__device__ float g_qdr[BB*HH*EE*8];             // q . base_rpr[p], p padded to 8
__device__ float g_o[BB*EE*DD];                 // attention output pre-FC, [b,e,h*32+d]
__device__ float g_asum[BB*EE];
__device__ int   g_acnt[BB*EE];
__device__ unsigned char g_d8[BB*EE*D8_LD];     // dist compressed: 0..3 valid, 255 masked

__device__ __forceinline__ float warp_sum(float v) {
    #pragma unroll
    for (int o = 16; o; o >>= 1) v += __shfl_xor_sync(0xffffffffu, v, o);
    return v;
}

// packed f32x2 helpers (sm_100+)
__device__ __forceinline__ void fma2(ull &d, ull a, ull b) {
    asm("fma.rn.f32x2 %0, %1, %2, %0;" : "+l"(d) : "l"(a), "l"(b));
}
__device__ __forceinline__ ull f2add(ull a, ull b) {
    ull d;
    asm("add.rn.f32x2 %0, %1, %2;" : "=l"(d) : "l"(a), "l"(b));
    return d;
}
__device__ __forceinline__ ull f2mul(ull a, ull b) {
    ull d;
    asm("mul.rn.f32x2 %0, %1, %2;" : "=l"(d) : "l"(a), "l"(b));
    return d;
}
__device__ __forceinline__ float f2sum(ull u) {
    float lo, hi;
    asm("mov.b64 {%0,%1}, %2;" : "=f"(lo), "=f"(hi) : "l"(u));
    return lo + hi;
}
__device__ __forceinline__ ull packf2(float x, float y) {
    ull u;
    asm("mov.b64 %0, {%1,%2};" : "=l"(u) : "f"(x), "f"(y));
    return u;
}
__device__ __forceinline__ ull shfl_xor_ull(ull v, int m) {
    unsigned lo = (unsigned)v, hi = (unsigned)(v >> 32);
    lo = __shfl_xor_sync(0xffffffffu, lo, m);
    hi = __shfl_xor_sync(0xffffffffu, hi, m);
    return ((ull)hi << 32) | lo;
}

// ---------------- mbarrier + bulk-copy helpers ----------------
__device__ __forceinline__ void mbar_init(unsigned a, unsigned cnt) {
    asm volatile("mbarrier.init.shared.b64 [%0], %1;" :: "r"(a), "r"(cnt) : "memory");
}
__device__ __forceinline__ void mbar_expect_tx(unsigned a, unsigned bytes) {
    asm volatile("mbarrier.arrive.expect_tx.shared.b64 _, [%0], %1;"
                 :: "r"(a), "r"(bytes) : "memory");
}
__device__ __forceinline__ void bulk_g2s(unsigned dst, const void* src, unsigned bytes, unsigned mbar) {
    asm volatile("cp.async.bulk.shared::cta.global.mbarrier::complete_tx::bytes [%0], [%1], %2, [%3];"
                 :: "r"(dst), "l"(src), "r"(bytes), "r"(mbar) : "memory");
}
#define MBAR_WAIT(addr, par) do { \
    asm volatile( \
        "{\n\t.reg .pred P;\n\t" \
        "WL%=:\n\t" \
        "mbarrier.try_wait.parity.acquire.cta.shared::cta.b64 P, [%0], %1, 0x989680;\n\t" \
        "@P bra WD%=;\n\t" \
        "bra WL%=;\n\t" \
        "WD%=:\n\t}" \
        :: "r"(addr), "r"(par) : "memory"); \
} while (0)

// ---------------- K0: zero accumulators ----------------
__global__ void zero_kernel() {
    int i = blockIdx.x * 256 + threadIdx.x;
    if (i < BB*EE) { g_asum[i] = 0.f; g_acnt[i] = 0; }
}

// ---------------- K0b: valid counts + d8 compression ----------------
__global__ void __launch_bounds__(256) countwrite_kernel(const int* __restrict__ dist) {
    int b  = blockIdx.y;
    int q0 = blockIdx.x * 8;
    int t  = threadIdx.x;
    const int* dpb = dist + (long long)b*EE*EE;
    unsigned char* d8 = g_d8 + (long long)b*EE*D8_LD;
    for (int k = t; k < EE; k += 256) {
        int cnt = 0;
        #pragma unroll
        for (int r = 0; r < 8; r++) {
            int q = q0 + r;
            if (q < EE) {
                int dv = dpb[(long long)q*EE + k];
                bool ok = (dv <= 3);
                d8[q*D8_LD + k] = ok ? (unsigned char)dv : (unsigned char)255;
                cnt += ok ? 1 : 0;
            }
        }
        atomicAdd(&g_acnt[b*EE + k], cnt);
    }
}

// ---------------- K1: layernorm + QKV projections (16 rows/block) ----------------
__global__ void __launch_bounds__(256) proj_kernel(
    const float* __restrict__ x,
    const float* __restrict__ Wq, const float* __restrict__ Wk,
    const float* __restrict__ Wv,
    const float* __restrict__ lnw, const float* __restrict__ lnb,
    const float* __restrict__ rpr)
{
    __shared__ __align__(16) float ssm[256*16];   // [d][r] raw input; later K transpose buf
    __shared__ __align__(16) float nsm[256*16];   // [d][r] layernormed
    int b  = blockIdx.y;
    int e0 = blockIdx.x * 16;
    int t  = threadIdx.x;
    const float* xb = x + b*(DD*EE);

    for (int i = t; i < 4096; i += 256) {
        int d = i >> 4, r = i & 15;
        int e = e0 + r;
        ssm[i] = (e < EE) ? xb[d*EE + e] : 0.f;
    }
    __syncthreads();

    int w = t >> 5, lane = t & 31;
    #pragma unroll
    for (int rr = 2*w; rr < 2*w + 2; rr++) {   // 2 rows per warp
        float s = 0.f;
        #pragma unroll
        for (int i = 0; i < 8; i++) s += ssm[(lane + 32*i)*16 + rr];
        s = warp_sum(s);
        float mu = s * (1.f/256.f);
        float vs = 0.f;
        #pragma unroll
        for (int i = 0; i < 8; i++) {
            float dlt = ssm[(lane + 32*i)*16 + rr] - mu;
            vs += dlt*dlt;
        }
        vs = warp_sum(vs);
        float rstd = rsqrtf(vs * (1.f/256.f) + 1e-6f);
        #pragma unroll
        for (int i = 0; i < 8; i++) {
            int d = lane + 32*i;
            nsm[d*16 + rr] = (ssm[d*16 + rr] - mu) * rstd * lnw[d] + lnb[d];
        }
    }
    __syncthreads();

    int j = t;
    float aq[16], ak[16], av[16];
    #pragma unroll
    for (int r = 0; r < 16; r++) { aq[r] = 0.f; ak[r] = 0.f; av[r] = 0.f; }

    #pragma unroll 2
    for (int d = 0; d < 256; d++) {
        float wq = Wq[d*256 + j];
        float wk = Wk[d*256 + j];
        float wv = Wv[d*256 + j];
        #pragma unroll
        for (int q4 = 0; q4 < 4; q4++) {
            float4 sv = *(const float4*)&ssm[d*16 + 4*q4];
            float4 nv = *(const float4*)&nsm[d*16 + 4*q4];
            aq[4*q4+0] += nv.x*wq; aq[4*q4+1] += nv.y*wq;
            aq[4*q4+2] += nv.z*wq; aq[4*q4+3] += nv.w*wq;
            ak[4*q4+0] += sv.x*wk; ak[4*q4+1] += sv.y*wk;
            ak[4*q4+2] += sv.z*wk; ak[4*q4+3] += sv.w*wk;
            av[4*q4+0] += sv.x*wv; av[4*q4+1] += sv.y*wv;
            av[4*q4+2] += sv.z*wv; av[4*q4+3] += sv.w*wv;
        }
    }

    int h = j >> 5, dk = j & 31;
    int bh = b*HH + h;
    const float inv_sqrt_dk = 0.17677669529663687f;  // 1/sqrt(32)
    float qsv[16];
    #pragma unroll
    for (int r = 0; r < 16; r++) qsv[r] = aq[r] * inv_sqrt_dk;

    #pragma unroll
    for (int r = 0; r < 16; r++) {
        int e = e0 + r;
        if (e < EE) {
            g_q[(bh*EE + e)*32 + dk] = qsv[r];
            g_v[((long long)bh*1536 + e)*32 + dk] = av[r];
        }
    }

    #pragma unroll
    for (int p = 0; p < 6; p++) {
        float rv = rpr[p*32 + lane];
        #pragma unroll
        for (int r = 0; r < 16; r++) {
            float pv = warp_sum(qsv[r] * rv);
            if (lane == 0 && (e0 + r) < EE)
                g_qdr[(bh*EE + (e0 + r))*8 + p] = pv;
        }
    }

    // ---- K pair-transpose into 24-chunk g_k2[bh][c][j16][p32] ----
    __syncthreads();                     // all ssm/nsm reads done
    #pragma unroll
    for (int r = 0; r < 16; r++) ssm[t*16 + r] = ak[r];   // ssm[(h*32+dk)][r]
    __syncthreads();
    {
        int hh = t >> 5;                 // 0..7
        int jj = (t >> 1) & 15;          // 0..15 d-pair
        int ph = t & 1;                  // which 4 of the 8 pairs
        const float* s0 = &ssm[(hh*32 + 2*jj    )*16];
        const float* s1 = &ssm[(hh*32 + 2*jj + 1)*16];
        int pg = e0 >> 1;                // multiple of 8
        int cc = pg >> 5, pl = pg & 31;
        long long base = (((long long)(b*HH + hh)*24 + cc)*16 + jj)*32 + pl + 4*ph;
        #pragma unroll
        for (int ps = 0; ps < 4; ps++) {
            int le = 8*ph + 2*ps;        // local e of even k
            ulonglong2 val;
            val.x = packf2(s0[le],   s1[le]);
            val.y = packf2(s0[le+1], s1[le+1]);
            g_k2[base + ps] = val;
        }
    }
}

// ---------------- K2: attention (256 threads, 8 q-rows, 3 CTAs/SM) ----------------
#define SC_LD 1512
// floats: mbar 16 + sc 8*1512 + 2 bufs (2*2048) + qsm 256 + qdr 64 + flaginv 8 + invr 8
#define SMEM_ATTN ((16 + 8*SC_LD + 2*2048 + 256 + 64 + 8 + 8)*4)
#define CHUNK_BYTES 8192u

__global__ void __launch_bounds__(256, 3) attn_kernel(float* __restrict__ out)
{
    extern __shared__ __align__(16) float sm[];
    float* sc      = sm + 16;                // 8 x 1512 scores (unnormalized exp)
    float* buf0f   = sc + 8*SC_LD;           // 8 KB staging x2
    float* buf1f   = buf0f + 2048;
    float* qsm     = buf1f + 2048;           // 8 x 32 scaled q
    float* qdr     = qsm + 256;              // 8 x 8 bias table
    float* flaginv = qdr + 64;               // 8
    float* invr    = flaginv + 8;            // 8

    int qt = blockIdx.x, h = blockIdx.y, b = blockIdx.z;
    int q0 = qt * 8;
    int t  = threadIdx.x;
    int w  = t >> 5, lane = t & 31;
    int bh = b*HH + h;

    unsigned smb = (unsigned)__cvta_generic_to_shared(sm);
    unsigned mbF0 = smb, mbF1 = smb + 8;
    unsigned bsm0 = (unsigned)__cvta_generic_to_shared(buf0f);
    unsigned bsm1 = (unsigned)__cvta_generic_to_shared(buf1f);

    const ulonglong2* k2base = g_k2 + (long long)bh*24*512;
    const float* vbase = g_v + (long long)bh*1536*32;
    const unsigned char* d8b = g_d8 + (long long)b*EE*D8_LD;

    // -------- prologue --------
    {
        int row = t >> 5;
        int qg = q0 + row;
        qsm[t] = (qg < EE) ? g_q[(bh*EE + qg)*32 + lane] : 0.f;
    }
    if (t < 64) {
        int qg = q0 + (t >> 3);
        qdr[t] = (qg < EE) ? g_qdr[(bh*EE + qg)*8 + (t & 7)] : 0.f;
    }
    if (t == 0) {
        mbar_init(mbF0, 1); mbar_init(mbF1, 1);
        mbar_expect_tx(mbF0, CHUNK_BYTES); bulk_g2s(bsm0, k2base,       CHUNK_BYTES, mbF0);
        mbar_expect_tx(mbF1, CHUNK_BYTES); bulk_g2s(bsm1, k2base + 512, CHUNK_BYTES, mbF1);
    }
    __syncthreads();

    // ================= score phase: 24 chunks of 64 k (32 pairs) =================
    // p = 8*(w&3) + (lane&7); r = 4*(w>>2) + (lane>>3)  -> conflict-free LDS128 phases
    int p  = 8*(w & 3) + (lane & 7);
    int r  = 4*(w >> 2) + (lane >> 3);
    int qg = q0 + r;

    ull qr[16];
    {
        const ull* a = (const ull*)(qsm + r*32);
        #pragma unroll
        for (int jj = 0; jj < 16; jj++) qr[jj] = a[jj];
    }
    float biasrow[4];
    *(float4*)biasrow = *(const float4*)&qdr[r*8];

    for (int c = 0; c < 24; c++) {
        int kc = c * 64;
        int kgA = kc + 2*p;
        unsigned mb = (c & 1) ? mbF1 : mbF0;
        int par = (c >> 1) & 1;

        uchar2 dA = make_uchar2(255, 255);
        if (qg < EE && kgA < EE)
            dA = *(const uchar2*)(d8b + (long long)qg*D8_LD + kgA);

        MBAR_WAIT(mb, par);

        const ulonglong2* prow = (const ulonglong2*)((c & 1) ? buf1f : buf0f) + p;
        ull a0 = 0, a1 = 0;
        #pragma unroll
        for (int jj = 0; jj < 16; jj++) {
            ulonglong2 kv = prow[jj*32];
            fma2(a0, qr[jj], kv.x);
            fma2(a1, qr[jj], kv.y);
        }

        if (kgA < EE) {
            float sa = -1e9f, sb = -1e9f;
            if (dA.x <= 3) sa = f2sum(a0) + biasrow[dA.x & 3];
            if (dA.y <= 3) sb = f2sum(a1) + biasrow[dA.y & 3];
            *(ull*)&sc[r*SC_LD + kgA] = packf2(sa, sb);
        }
        __syncthreads();
        if (t == 0 && c < 22) {
            mbar_expect_tx(mb, CHUNK_BYTES);
            bulk_g2s((c & 1) ? bsm1 : bsm0, k2base + (c + 2)*512, CHUNK_BYTES, mb);
        }
    }

    // issue V chunks 0,1 (overlap with softmax)
    if (t == 0) {
        mbar_expect_tx(mbF0, CHUNK_BYTES); bulk_g2s(bsm0, vbase,        CHUNK_BYTES, mbF0);
        mbar_expect_tx(mbF1, CHUNK_BYTES); bulk_g2s(bsm1, vbase + 2048, CHUNK_BYTES, mbF1);
    }

    // ===== softmax (one row per warp), 2-pass (masked -1e9 underflows to 0) =====
    {
        int rr = w;
        int qgr = q0 + rr;
        if (qgr < EE) {
            float* row = sc + rr*SC_LD;
            float sum = 0.f;
            for (int k = lane*4; k < EE; k += 128) {
                float4 v = *(float4*)&row[k];
                v.x = __expf(v.x); v.y = __expf(v.y);
                v.z = __expf(v.z); v.w = __expf(v.w);
                *(float4*)&row[k] = v;
                sum += (v.x + v.y) + (v.z + v.w);
            }
            sum = warp_sum(sum);
            bool fullmask = (sum == 0.f);
            if (fullmask) {
                for (int k = lane*4; k < EE; k += 128)
                    *(float4*)&row[k] = make_float4(1.f, 1.f, 1.f, 1.f);
                sum = (float)EE;
            }
            float inv = 1.f / sum;
            if (lane == 0) {
                invr[rr] = inv;
                flaginv[rr] = fullmask ? 0.f : inv;
            }
            long long obase = (long long)O_ATTN + (long long)(bh*EE + qgr)*EE;
            for (int k = lane*4; k < EE; k += 128) {
                float4 v = *(const float4*)&row[k];
                v.x *= inv; v.y *= inv; v.z *= inv; v.w *= inv;
                *(float4*)&out[obase + k] = v;
            }
        } else {
            if (lane == 0) { invr[rr] = 0.f; flaginv[rr] = 0.f; }
        }
    }
    __syncthreads();

    // column sums (unnormalized exp * flaginv)
    for (int k = t; k < EE; k += 256) {
        float s = 0.f;
        #pragma unroll
        for (int rr = 0; rr < 8; rr++) s += sc[rr*SC_LD + k] * flaginv[rr];
        atomicAdd(&g_asum[b*EE + k], s);
    }

    // ================= AV: 24 chunks of 64 k =================
    // thread = (ks = t>>3 in 0..31 slicing 2 k, dp = t&7 float4 of d); owns all 8 rows
    int ks = t >> 3;
    int dp = t & 7;
    ull accL[8], accH[8];
    #pragma unroll
    for (int rr = 0; rr < 8; rr++) { accL[rr] = 0; accH[rr] = 0; }

    for (int c = 0; c < 24; c++) {
        int kc = c * 64;
        unsigned mb = (c & 1) ? mbF1 : mbF0;
        int par = (c >> 1) & 1;
        MBAR_WAIT(mb, par);
        const float4* bp4 = (const float4*)((c & 1) ? buf1f : buf0f);

        int kg0 = kc + 2*ks;
        if (kg0 < EE) {
            float4 vva = bp4[(2*ks    )*8 + dp];
            float4 vvb = bp4[(2*ks + 1)*8 + dp];
            ull v0a = packf2(vva.x, vva.y), v1a = packf2(vva.z, vva.w);
            ull v0b = packf2(vvb.x, vvb.y), v1b = packf2(vvb.z, vvb.w);
            #pragma unroll
            for (int rr = 0; rr < 8; rr++) {
                float2 a = *(const float2*)&sc[rr*SC_LD + kg0];
                ull s0 = packf2(a.x, a.x);
                ull s1 = packf2(a.y, a.y);
                fma2(accL[rr], s0, v0a); fma2(accH[rr], s0, v1a);
                fma2(accL[rr], s1, v0b); fma2(accH[rr], s1, v1b);
            }
        }
        __syncthreads();
        if (t == 0 && c < 22) {
            mbar_expect_tx(mb, CHUNK_BYTES);
            bulk_g2s((c & 1) ? bsm1 : bsm0, vbase + (long long)(c + 2)*2048, CHUNK_BYTES, mb);
        }
    }

    // intra-warp reduction over 4 k-slices (lane bits 3,4)
    #pragma unroll
    for (int rr = 0; rr < 8; rr++) {
        accL[rr] = f2add(accL[rr], shfl_xor_ull(accL[rr], 8));
        accL[rr] = f2add(accL[rr], shfl_xor_ull(accL[rr], 16));
        accH[rr] = f2add(accH[rr], shfl_xor_ull(accH[rr], 8));
        accH[rr] = f2add(accH[rr], shfl_xor_ull(accH[rr], 16));
    }

    // cross-warp reduction via smem partials (sc region free now)
    {
        ulonglong2* part = (ulonglong2*)sc;   // [w][row][dp]: 8*8*8 ull2 = 8 KB
        if (lane < 8) {
            #pragma unroll
            for (int rr = 0; rr < 8; rr++) {
                ulonglong2 v; v.x = accL[rr]; v.y = accH[rr];
                part[(w*8 + rr)*8 + dp] = v;
            }
        }
    }
    __syncthreads();
    if (t < 64) {
        const ulonglong2* part = (const ulonglong2*)sc;
        int row = t >> 3, dpp = t & 7;
        ull sA = 0, sB = 0;
        #pragma unroll
        for (int ww = 0; ww < 8; ww++) {
            ulonglong2 v = part[(ww*8 + row)*8 + dpp];
            sA = f2add(sA, v.x);
            sB = f2add(sB, v.y);
        }
        int qgr = q0 + row;
        if (qgr < EE) {
            float iv = invr[row];
            ull ivp = packf2(iv, iv);
            ulonglong2 o;
            o.x = f2mul(sA, ivp);
            o.y = f2mul(sB, ivp);
            *(ulonglong2*)&g_o[(b*EE + qgr)*DD + h*32 + 4*dpp] = o;
        }
    }
}

// ---------------- K3: FC + residual + transpose-out ----------------
__global__ void __launch_bounds__(256) fc_kernel(
    const float* __restrict__ x, const float* __restrict__ Wfc,
    float* __restrict__ out)
{
    __shared__ __align__(16) float osm[256*8];   // [d][r]
    int b  = blockIdx.y;
    int e0 = blockIdx.x * 8;
    int t  = threadIdx.x;

    for (int i = t; i < 2048; i += 256) {
        int r = i >> 8, d = i & 255;
        int e = e0 + r;
        osm[d*8 + r] = (e < EE) ? g_o[(b*EE + e)*DD + d] : 0.f;
    }
    __syncthreads();

    int j = t;
    const float* xb = x + b*DD*EE + j*EE;
    float acc[8];
    #pragma unroll
    for (int r = 0; r < 8; r++) {
        int e = e0 + r;
        acc[r] = (e < EE) ? xb[e] : 0.f;   // residual
    }
    #pragma unroll 4
    for (int d = 0; d < 256; d++) {
        float wv = Wfc[d*256 + j];
        float4 o0 = *(const float4*)&osm[d*8];
        float4 o1 = *(const float4*)&osm[d*8 + 4];
        acc[0] += o0.x*wv; acc[1] += o0.y*wv; acc[2] += o0.z*wv; acc[3] += o0.w*wv;
        acc[4] += o1.x*wv; acc[5] += o1.y*wv; acc[6] += o1.z*wv; acc[7] += o1.w*wv;
    }
    float* ob = out + b*DD*EE + j*EE + e0;
    if (e0 + 8 <= EE) {
        *(float4*)ob       = make_float4(acc[0], acc[1], acc[2], acc[3]);
        *(float4*)(ob + 4) = make_float4(acc[4], acc[5], acc[6], acc[7]);
    } else {
        for (int r = 0; r < 8; r++)
            if (e0 + r < EE) ob[r] = acc[r];
    }
}

// ---------------- K4: attn_per_edge ----------------
__global__ void finalize_kernel(float* __restrict__ out) {
    int i = blockIdx.x * 256 + threadIdx.x;
    if (i < BB*EE) {
        out[O_APE + i] = g_asum[i] / (float)g_acnt[i];
    }
}

// ---------------- launch ----------------
extern "C" void kernel_launch(void* const* d_in, const int* in_sizes, int n_in,
                              void* d_out, int out_size)
{
    const float* x    = (const float*)d_in[0];
    const int*   dist = (const int*)  d_in[1];
    const float* Wq   = (const float*)d_in[2];
    const float* Wk   = (const float*)d_in[3];
    const float* Wv   = (const float*)d_in[4];
    const float* Wfc  = (const float*)d_in[5];
    const float* lnw  = (const float*)d_in[6];
    const float* lnb  = (const float*)d_in[7];
    const float* rpr  = (const float*)d_in[8];
    float* out = (float*)d_out;

    cudaFuncSetAttribute(attn_kernel,
        cudaFuncAttributeMaxDynamicSharedMemorySize, SMEM_ATTN);

    zero_kernel<<<24, 256>>>();

    dim3 gc(188, BB);
    countwrite_kernel<<<gc, 256>>>(dist);

    dim3 g1(94, BB);
    proj_kernel<<<g1, 256>>>(x, Wq, Wk, Wv, lnw, lnb, rpr);

    dim3 g2(188, HH, BB);
    attn_kernel<<<g2, 256, SMEM_ATTN>>>(out);

    dim3 g3(188, BB);
    fc_kernel<<<g3, 256>>>(x, Wfc, out);

    finalize_kernel<<<24, 256>>>(out);
}

// round 13
// speedup vs baseline: 1.1152x; 1.0273x over previous
#include <cuda_runtime.h>

#define BB 4
#define EE 1500
#define DD 256
#define HH 8
#define DK 32

#define O_ATTN 1536000
#define O_APE  73536000
#define D8_LD 1504

typedef unsigned long long ull;

// ---------------- scratch (no allocation allowed) ----------------
__device__ float g_q[BB*HH*EE*DK];              // scaled q, [b,h,e,dk]
__device__ ulonglong2 g_k2[BB*HH*24*512];       // K pair-transposed, 24 chunks: [bh][c][j16][p32]
__device__ float g_v[BB*HH*1536*DK];            // V natural [k][d], padded to 1536 rows
__device__ float g_qdr[BB*HH*EE*8];             // q . base_rpr[p], p padded to 8
__device__ float g_o[BB*EE*DD];                 // attention output pre-FC, [b,e,h*32+d]
__device__ float g_asum[BB*EE];
__device__ int   g_acnt[BB*EE];
__device__ unsigned char g_d8[BB*EE*D8_LD];     // dist compressed: 0..3 valid, 255 masked

__device__ __forceinline__ float warp_sum(float v) {
    #pragma unroll
    for (int o = 16; o; o >>= 1) v += __shfl_xor_sync(0xffffffffu, v, o);
    return v;
}

// packed f32x2 helpers (sm_100+)
__device__ __forceinline__ void fma2(ull &d, ull a, ull b) {
    asm("fma.rn.f32x2 %0, %1, %2, %0;" : "+l"(d) : "l"(a), "l"(b));
}
__device__ __forceinline__ ull f2add(ull a, ull b) {
    ull d;
    asm("add.rn.f32x2 %0, %1, %2;" : "=l"(d) : "l"(a), "l"(b));
    return d;
}
__device__ __forceinline__ ull f2mul(ull a, ull b) {
    ull d;
    asm("mul.rn.f32x2 %0, %1, %2;" : "=l"(d) : "l"(a), "l"(b));
    return d;
}
__device__ __forceinline__ float f2sum(ull u) {
    float lo, hi;
    asm("mov.b64 {%0,%1}, %2;" : "=f"(lo), "=f"(hi) : "l"(u));
    return lo + hi;
}
__device__ __forceinline__ ull packf2(float x, float y) {
    ull u;
    asm("mov.b64 %0, {%1,%2};" : "=l"(u) : "f"(x), "f"(y));
    return u;
}
__device__ __forceinline__ ull shfl_xor_ull(ull v, int m) {
    unsigned lo = (unsigned)v, hi = (unsigned)(v >> 32);
    lo = __shfl_xor_sync(0xffffffffu, lo, m);
    hi = __shfl_xor_sync(0xffffffffu, hi, m);
    return ((ull)hi << 32) | lo;
}

// ---------------- mbarrier + bulk-copy helpers ----------------
__device__ __forceinline__ void mbar_init(unsigned a, unsigned cnt) {
    asm volatile("mbarrier.init.shared.b64 [%0], %1;" :: "r"(a), "r"(cnt) : "memory");
}
__device__ __forceinline__ void mbar_expect_tx(unsigned a, unsigned bytes) {
    asm volatile("mbarrier.arrive.expect_tx.shared.b64 _, [%0], %1;"
                 :: "r"(a), "r"(bytes) : "memory");
}
__device__ __forceinline__ void bulk_g2s(unsigned dst, const void* src, unsigned bytes, unsigned mbar) {
    asm volatile("cp.async.bulk.shared::cta.global.mbarrier::complete_tx::bytes [%0], [%1], %2, [%3];"
                 :: "r"(dst), "l"(src), "r"(bytes), "r"(mbar) : "memory");
}
#define MBAR_WAIT(addr, par) do { \
    asm volatile( \
        "{\n\t.reg .pred P;\n\t" \
        "WL%=:\n\t" \
        "mbarrier.try_wait.parity.acquire.cta.shared::cta.b64 P, [%0], %1, 0x989680;\n\t" \
        "@P bra WD%=;\n\t" \
        "bra WL%=;\n\t" \
        "WD%=:\n\t}" \
        :: "r"(addr), "r"(par) : "memory"); \
} while (0)

// ---------------- K0: zero accumulators ----------------
__global__ void zero_kernel() {
    int i = blockIdx.x * 256 + threadIdx.x;
    if (i < BB*EE) { g_asum[i] = 0.f; g_acnt[i] = 0; }
}

// ---------------- K0b: valid counts + d8 compression ----------------
__global__ void __launch_bounds__(256) countwrite_kernel(const int* __restrict__ dist) {
    int b  = blockIdx.y;
    int q0 = blockIdx.x * 8;
    int t  = threadIdx.x;
    const int* dpb = dist + (long long)b*EE*EE;
    unsigned char* d8 = g_d8 + (long long)b*EE*D8_LD;
    for (int k = t; k < EE; k += 256) {
        int cnt = 0;
        #pragma unroll
        for (int r = 0; r < 8; r++) {
            int q = q0 + r;
            if (q < EE) {
                int dv = dpb[(long long)q*EE + k];
                bool ok = (dv <= 3);
                d8[q*D8_LD + k] = ok ? (unsigned char)dv : (unsigned char)255;
                cnt += ok ? 1 : 0;
            }
        }
        atomicAdd(&g_acnt[b*EE + k], cnt);
    }
}

// ---------------- K1: layernorm + QKV projections (8 rows/block) ----------------
__global__ void __launch_bounds__(256) proj_kernel(
    const float* __restrict__ x,
    const float* __restrict__ Wq, const float* __restrict__ Wk,
    const float* __restrict__ Wv,
    const float* __restrict__ lnw, const float* __restrict__ lnb,
    const float* __restrict__ rpr)
{
    __shared__ __align__(16) float ssm[256*8];   // [d][r] raw input; later K transpose buf
    __shared__ __align__(16) float nsm[256*8];   // [d][r] layernormed
    int b  = blockIdx.y;
    int e0 = blockIdx.x * 8;
    int t  = threadIdx.x;
    const float* xb = x + b*(DD*EE);

    for (int i = t; i < 2048; i += 256) {
        int d = i >> 3, r = i & 7;
        int e = e0 + r;
        ssm[i] = (e < EE) ? xb[d*EE + e] : 0.f;
    }
    __syncthreads();

    int w = t >> 5, lane = t & 31;
    {   // layernorm of row w (one row per warp)
        float s = 0.f;
        #pragma unroll
        for (int i = 0; i < 8; i++) s += ssm[(lane + 32*i)*8 + w];
        s = warp_sum(s);
        float mu = s * (1.f/256.f);
        float vs = 0.f;
        #pragma unroll
        for (int i = 0; i < 8; i++) {
            float dlt = ssm[(lane + 32*i)*8 + w] - mu;
            vs += dlt*dlt;
        }
        vs = warp_sum(vs);
        float rstd = rsqrtf(vs * (1.f/256.f) + 1e-6f);
        #pragma unroll
        for (int i = 0; i < 8; i++) {
            int d = lane + 32*i;
            nsm[d*8 + w] = (ssm[d*8 + w] - mu) * rstd * lnw[d] + lnb[d];
        }
    }
    __syncthreads();

    int j = t;
    float aq[8], ak[8], av[8];
    #pragma unroll
    for (int r = 0; r < 8; r++) { aq[r] = 0.f; ak[r] = 0.f; av[r] = 0.f; }

    #pragma unroll 4
    for (int d = 0; d < 256; d++) {
        float wq = Wq[d*256 + j];
        float wk = Wk[d*256 + j];
        float wv = Wv[d*256 + j];
        float4 s0 = *(const float4*)&ssm[d*8];
        float4 s1 = *(const float4*)&ssm[d*8 + 4];
        float4 n0 = *(const float4*)&nsm[d*8];
        float4 n1 = *(const float4*)&nsm[d*8 + 4];
        aq[0] += n0.x*wq; aq[1] += n0.y*wq; aq[2] += n0.z*wq; aq[3] += n0.w*wq;
        aq[4] += n1.x*wq; aq[5] += n1.y*wq; aq[6] += n1.z*wq; aq[7] += n1.w*wq;
        ak[0] += s0.x*wk; ak[1] += s0.y*wk; ak[2] += s0.z*wk; ak[3] += s0.w*wk;
        ak[4] += s1.x*wk; ak[5] += s1.y*wk; ak[6] += s1.z*wk; ak[7] += s1.w*wk;
        av[0] += s0.x*wv; av[1] += s0.y*wv; av[2] += s0.z*wv; av[3] += s0.w*wv;
        av[4] += s1.x*wv; av[5] += s1.y*wv; av[6] += s1.z*wv; av[7] += s1.w*wv;
    }

    int h = j >> 5, dk = j & 31;
    int bh = b*HH + h;
    const float inv_sqrt_dk = 0.17677669529663687f;  // 1/sqrt(32)
    float qsv[8];
    #pragma unroll
    for (int r = 0; r < 8; r++) qsv[r] = aq[r] * inv_sqrt_dk;

    #pragma unroll
    for (int r = 0; r < 8; r++) {
        int e = e0 + r;
        if (e < EE) {
            g_q[(bh*EE + e)*32 + dk] = qsv[r];
            g_v[((long long)bh*1536 + e)*32 + dk] = av[r];
        }
    }

    #pragma unroll
    for (int p = 0; p < 6; p++) {
        float rv = rpr[p*32 + lane];
        #pragma unroll
        for (int r = 0; r < 8; r++) {
            float pv = warp_sum(qsv[r] * rv);
            if (lane == 0 && (e0 + r) < EE)
                g_qdr[(bh*EE + (e0 + r))*8 + p] = pv;
        }
    }

    // ---- K pair-transpose into 24-chunk g_k2[bh][c][j16][p32] ----
    __syncthreads();                     // all ssm/nsm reads done
    #pragma unroll
    for (int r = 0; r < 8; r++) ssm[t*8 + r] = ak[r];   // ssm[(h*32+dk)][r]
    __syncthreads();
    {
        int hh = t >> 5;                 // 0..7
        int jj = (t >> 1) & 15;          // 0..15 d-pair
        int ph = t & 1;                  // which half of the 4 pairs
        const float* s0 = &ssm[(hh*32 + 2*jj    )*8];
        const float* s1 = &ssm[(hh*32 + 2*jj + 1)*8];
        int pg = e0 >> 1;                // first pair (multiple of 4)
        int cc = pg >> 5, pl = pg & 31;
        long long base = (((long long)(b*HH + hh)*24 + cc)*16 + jj)*32 + pl + 2*ph;
        #pragma unroll
        for (int ps = 0; ps < 2; ps++) {
            int ee = 4*ph + 2*ps;        // local e of even k
            ulonglong2 val;
            val.x = packf2(s0[ee],   s1[ee]);
            val.y = packf2(s0[ee+1], s1[ee+1]);
            g_k2[base + ps] = val;
        }
    }
}

// ---------------- K2: attention (256 threads, 8 q-rows, 3 CTAs/SM) ----------------
#define SC_LD 1512
// floats: mbar 16 + sc 8*1512 + 2 bufs (2*2048) + qsm 256 + qdr 64 + flaginv 8 + invr 8
#define SMEM_ATTN ((16 + 8*SC_LD + 2*2048 + 256 + 64 + 8 + 8)*4)
#define CHUNK_BYTES 8192u

__global__ void __launch_bounds__(256, 3) attn_kernel(float* __restrict__ out)
{
    extern __shared__ __align__(16) float sm[];
    float* sc      = sm + 16;                // 8 x 1512 scores (unnormalized exp)
    float* buf0f   = sc + 8*SC_LD;           // 8 KB staging x2
    float* buf1f   = buf0f + 2048;
    float* qsm     = buf1f + 2048;           // 8 x 32 scaled q
    float* qdr     = qsm + 256;              // 8 x 8 bias table
    float* flaginv = qdr + 64;               // 8
    float* invr    = flaginv + 8;            // 8

    int qt = blockIdx.x, h = blockIdx.y, b = blockIdx.z;
    int q0 = qt * 8;
    int t  = threadIdx.x;
    int w  = t >> 5, lane = t & 31;
    int bh = b*HH + h;

    unsigned smb = (unsigned)__cvta_generic_to_shared(sm);
    unsigned mbF0 = smb, mbF1 = smb + 8;
    unsigned bsm0 = (unsigned)__cvta_generic_to_shared(buf0f);
    unsigned bsm1 = (unsigned)__cvta_generic_to_shared(buf1f);

    const ulonglong2* k2base = g_k2 + (long long)bh*24*512;
    const float* vbase = g_v + (long long)bh*1536*32;
    const unsigned char* d8b = g_d8 + (long long)b*EE*D8_LD;

    // -------- prologue --------
    {
        int row = t >> 5;
        int qg = q0 + row;
        qsm[t] = (qg < EE) ? g_q[(bh*EE + qg)*32 + lane] : 0.f;
    }
    if (t < 64) {
        int qg = q0 + (t >> 3);
        qdr[t] = (qg < EE) ? g_qdr[(bh*EE + qg)*8 + (t & 7)] : 0.f;
    }
    if (t == 0) {
        mbar_init(mbF0, 1); mbar_init(mbF1, 1);
        mbar_expect_tx(mbF0, CHUNK_BYTES); bulk_g2s(bsm0, k2base,       CHUNK_BYTES, mbF0);
        mbar_expect_tx(mbF1, CHUNK_BYTES); bulk_g2s(bsm1, k2base + 512, CHUNK_BYTES, mbF1);
    }
    __syncthreads();

    // ================= score phase: 24 chunks of 64 k (32 pairs) =================
    // lanes: pl = lane&3 (p within quad), rg2 = (lane>>2)&3 (row), jh = lane>>4 (j half)
    // thread: pair p = 4w + pl, rows {rg2, rg2+4}, j in [8*jh, 8*jh+8)
    // partial dot products combined across jh via one shfl_xor(16) round.
    {
        int pl  = lane & 3;
        int rg2 = (lane >> 2) & 3;
        int jh  = lane >> 4;
        int p   = 4*w + pl;
        int r0 = rg2, r1 = rg2 + 4;
        int qg0 = q0 + r0, qg1 = q0 + r1;

        ull qr0[8], qr1[8];
        {
            const ull* a  = (const ull*)(qsm + r0*32) + jh*8;
            const ull* b2 = (const ull*)(qsm + r1*32) + jh*8;
            #pragma unroll
            for (int jj = 0; jj < 8; jj++) { qr0[jj] = a[jj]; qr1[jj] = b2[jj]; }
        }
        float biasA[4], biasB[4];
        *(float4*)biasA = *(const float4*)&qdr[r0*8];
        *(float4*)biasB = *(const float4*)&qdr[r1*8];

        uchar2 dA = make_uchar2(255, 255), dB = make_uchar2(255, 255);
        if (qg0 < EE) dA = *(const uchar2*)(d8b + (long long)qg0*D8_LD + 2*p);
        if (qg1 < EE) dB = *(const uchar2*)(d8b + (long long)qg1*D8_LD + 2*p);

        for (int c = 0; c < 24; c++) {
            int kc = c * 64;
            int kgA = kc + 2*p;
            unsigned mb = (c & 1) ? mbF1 : mbF0;
            int par = (c >> 1) & 1;

            // prefetch next chunk's d8
            uchar2 eA = make_uchar2(255, 255), eB = make_uchar2(255, 255);
            if (c < 23) {
                int kg2 = kc + 64 + 2*p;
                if (kg2 < EE) {
                    if (qg0 < EE) eA = *(const uchar2*)(d8b + (long long)qg0*D8_LD + kg2);
                    if (qg1 < EE) eB = *(const uchar2*)(d8b + (long long)qg1*D8_LD + kg2);
                }
            }

            MBAR_WAIT(mb, par);

            const ulonglong2* prow = (const ulonglong2*)((c & 1) ? buf1f : buf0f) + p;
            ull a0E = 0, a0O = 0, a1E = 0, a1O = 0;
            #pragma unroll
            for (int jj = 0; jj < 8; jj++) {
                ulonglong2 kv = prow[(jh*8 + jj)*32];
                fma2(a0E, qr0[jj], kv.x); fma2(a0O, qr0[jj], kv.y);
                fma2(a1E, qr1[jj], kv.x); fma2(a1O, qr1[jj], kv.y);
            }
            // combine j-halves (jh partner = lane ^ 16)
            a0E = f2add(a0E, shfl_xor_ull(a0E, 16));
            a0O = f2add(a0O, shfl_xor_ull(a0O, 16));
            a1E = f2add(a1E, shfl_xor_ull(a1E, 16));
            a1O = f2add(a1O, shfl_xor_ull(a1O, 16));

            if (jh == 0 && kgA < EE) {
                float sa = -1e9f, sb = -1e9f;
                if (dA.x <= 3) sa = f2sum(a0E) + biasA[dA.x & 3];
                if (dA.y <= 3) sb = f2sum(a0O) + biasA[dA.y & 3];
                *(ull*)&sc[r0*SC_LD + kgA] = packf2(sa, sb);
                sa = -1e9f; sb = -1e9f;
                if (dB.x <= 3) sa = f2sum(a1E) + biasB[dB.x & 3];
                if (dB.y <= 3) sb = f2sum(a1O) + biasB[dB.y & 3];
                *(ull*)&sc[r1*SC_LD + kgA] = packf2(sa, sb);
            }
            __syncthreads();
            if (t == 0 && c < 22) {
                mbar_expect_tx(mb, CHUNK_BYTES);
                bulk_g2s((c & 1) ? bsm1 : bsm0, k2base + (c + 2)*512, CHUNK_BYTES, mb);
            }
            dA = eA; dB = eB;
        }
    }

    // issue V chunks 0,1 (overlap with softmax)
    if (t == 0) {
        mbar_expect_tx(mbF0, CHUNK_BYTES); bulk_g2s(bsm0, vbase,        CHUNK_BYTES, mbF0);
        mbar_expect_tx(mbF1, CHUNK_BYTES); bulk_g2s(bsm1, vbase + 2048, CHUNK_BYTES, mbF1);
    }

    // ===== softmax (one row per warp), 2-pass (masked -1e9 underflows to 0) =====
    {
        int rr = w;
        int qgr = q0 + rr;
        if (qgr < EE) {
            float* row = sc + rr*SC_LD;
            float sum = 0.f;
            for (int k = lane*4; k < EE; k += 128) {
                float4 v = *(float4*)&row[k];
                v.x = __expf(v.x); v.y = __expf(v.y);
                v.z = __expf(v.z); v.w = __expf(v.w);
                *(float4*)&row[k] = v;
                sum += (v.x + v.y) + (v.z + v.w);
            }
            sum = warp_sum(sum);
            bool fullmask = (sum == 0.f);
            if (fullmask) {
                for (int k = lane*4; k < EE; k += 128)
                    *(float4*)&row[k] = make_float4(1.f, 1.f, 1.f, 1.f);
                sum = (float)EE;
            }
            float inv = 1.f / sum;
            if (lane == 0) {
                invr[rr] = inv;
                flaginv[rr] = fullmask ? 0.f : inv;
            }
            long long obase = (long long)O_ATTN + (long long)(bh*EE + qgr)*EE;
            for (int k = lane*4; k < EE; k += 128) {
                float4 v = *(const float4*)&row[k];
                v.x *= inv; v.y *= inv; v.z *= inv; v.w *= inv;
                *(float4*)&out[obase + k] = v;
            }
        } else {
            if (lane == 0) { invr[rr] = 0.f; flaginv[rr] = 0.f; }
        }
    }
    __syncthreads();

    // column sums (unnormalized exp * flaginv)
    for (int k = t; k < EE; k += 256) {
        float s = 0.f;
        #pragma unroll
        for (int rr = 0; rr < 8; rr++) s += sc[rr*SC_LD + k] * flaginv[rr];
        atomicAdd(&g_asum[b*EE + k], s);
    }

    // ================= AV: 24 chunks of 64 k =================
    // thread = (ks = t>>3 in 0..31 slicing 2 k, dp = t&7 float4 of d); owns all 8 rows
    int ks = t >> 3;
    int dp = t & 7;
    ull accL[8], accH[8];
    #pragma unroll
    for (int rr = 0; rr < 8; rr++) { accL[rr] = 0; accH[rr] = 0; }

    for (int c = 0; c < 24; c++) {
        int kc = c * 64;
        unsigned mb = (c & 1) ? mbF1 : mbF0;
        int par = (c >> 1) & 1;
        MBAR_WAIT(mb, par);
        const float4* bp4 = (const float4*)((c & 1) ? buf1f : buf0f);

        int kg0 = kc + 2*ks;
        if (kg0 < EE) {
            float4 vva = bp4[(2*ks    )*8 + dp];
            float4 vvb = bp4[(2*ks + 1)*8 + dp];
            ull v0a = packf2(vva.x, vva.y), v1a = packf2(vva.z, vva.w);
            ull v0b = packf2(vvb.x, vvb.y), v1b = packf2(vvb.z, vvb.w);
            #pragma unroll
            for (int rr = 0; rr < 8; rr++) {
                float2 a = *(const float2*)&sc[rr*SC_LD + kg0];
                ull s0 = packf2(a.x, a.x);
                ull s1 = packf2(a.y, a.y);
                fma2(accL[rr], s0, v0a); fma2(accH[rr], s0, v1a);
                fma2(accL[rr], s1, v0b); fma2(accH[rr], s1, v1b);
            }
        }
        __syncthreads();
        if (t == 0 && c < 22) {
            mbar_expect_tx(mb, CHUNK_BYTES);
            bulk_g2s((c & 1) ? bsm1 : bsm0, vbase + (long long)(c + 2)*2048, CHUNK_BYTES, mb);
        }
    }

    // intra-warp reduction over 4 k-slices (lane bits 3,4)
    #pragma unroll
    for (int rr = 0; rr < 8; rr++) {
        accL[rr] = f2add(accL[rr], shfl_xor_ull(accL[rr], 8));
        accL[rr] = f2add(accL[rr], shfl_xor_ull(accL[rr], 16));
        accH[rr] = f2add(accH[rr], shfl_xor_ull(accH[rr], 8));
        accH[rr] = f2add(accH[rr], shfl_xor_ull(accH[rr], 16));
    }

    // cross-warp reduction via smem partials (sc region free now)
    {
        ulonglong2* part = (ulonglong2*)sc;   // [w][row][dp]: 8*8*8 ull2 = 8 KB
        if (lane < 8) {
            #pragma unroll
            for (int rr = 0; rr < 8; rr++) {
                ulonglong2 v; v.x = accL[rr]; v.y = accH[rr];
                part[(w*8 + rr)*8 + dp] = v;
            }
        }
    }
    __syncthreads();
    if (t < 64) {
        const ulonglong2* part = (const ulonglong2*)sc;
        int row = t >> 3, dpp = t & 7;
        ull sA = 0, sB = 0;
        #pragma unroll
        for (int ww = 0; ww < 8; ww++) {
            ulonglong2 v = part[(ww*8 + row)*8 + dpp];
            sA = f2add(sA, v.x);
            sB = f2add(sB, v.y);
        }
        int qgr = q0 + row;
        if (qgr < EE) {
            float iv = invr[row];
            ull ivp = packf2(iv, iv);
            ulonglong2 o;
            o.x = f2mul(sA, ivp);
            o.y = f2mul(sB, ivp);
            *(ulonglong2*)&g_o[(b*EE + qgr)*DD + h*32 + 4*dpp] = o;
        }
    }
}

// ---------------- K3: FC + residual + transpose-out ----------------
__global__ void __launch_bounds__(256) fc_kernel(
    const float* __restrict__ x, const float* __restrict__ Wfc,
    float* __restrict__ out)
{
    __shared__ __align__(16) float osm[256*8];   // [d][r]
    int b  = blockIdx.y;
    int e0 = blockIdx.x * 8;
    int t  = threadIdx.x;

    for (int i = t; i < 2048; i += 256) {
        int r = i >> 8, d = i & 255;
        int e = e0 + r;
        osm[d*8 + r] = (e < EE) ? g_o[(b*EE + e)*DD + d] : 0.f;
    }
    __syncthreads();

    int j = t;
    const float* xb = x + b*DD*EE + j*EE;
    float acc[8];
    #pragma unroll
    for (int r = 0; r < 8; r++) {
        int e = e0 + r;
        acc[r] = (e < EE) ? xb[e] : 0.f;   // residual
    }
    #pragma unroll 4
    for (int d = 0; d < 256; d++) {
        float wv = Wfc[d*256 + j];
        float4 o0 = *(const float4*)&osm[d*8];
        float4 o1 = *(const float4*)&osm[d*8 + 4];
        acc[0] += o0.x*wv; acc[1] += o0.y*wv; acc[2] += o0.z*wv; acc[3] += o0.w*wv;
        acc[4] += o1.x*wv; acc[5] += o1.y*wv; acc[6] += o1.z*wv; acc[7] += o1.w*wv;
    }
    float* ob = out + b*DD*EE + j*EE + e0;
    if (e0 + 8 <= EE) {
        *(float4*)ob       = make_float4(acc[0], acc[1], acc[2], acc[3]);
        *(float4*)(ob + 4) = make_float4(acc[4], acc[5], acc[6], acc[7]);
    } else {
        for (int r = 0; r < 8; r++)
            if (e0 + r < EE) ob[r] = acc[r];
    }
}

// ---------------- K4: attn_per_edge ----------------
__global__ void finalize_kernel(float* __restrict__ out) {
    int i = blockIdx.x * 256 + threadIdx.x;
    if (i < BB*EE) {
        out[O_APE + i] = g_asum[i] / (float)g_acnt[i];
    }
}

// ---------------- launch ----------------
extern "C" void kernel_launch(void* const* d_in, const int* in_sizes, int n_in,
                              void* d_out, int out_size)
{
    const float* x    = (const float*)d_in[0];
    const int*   dist = (const int*)  d_in[1];
    const float* Wq   = (const float*)d_in[2];
    const float* Wk   = (const float*)d_in[3];
    const float* Wv   = (const float*)d_in[4];
    const float* Wfc  = (const float*)d_in[5];
    const float* lnw  = (const float*)d_in[6];
    const float* lnb  = (const float*)d_in[7];
    const float* rpr  = (const float*)d_in[8];
    float* out = (float*)d_out;

    cudaFuncSetAttribute(attn_kernel,
        cudaFuncAttributeMaxDynamicSharedMemorySize, SMEM_ATTN);

    zero_kernel<<<24, 256>>>();

    dim3 gc(188, BB);
    countwrite_kernel<<<gc, 256>>>(dist);

    dim3 g1(188, BB);
    proj_kernel<<<g1, 256>>>(x, Wq, Wk, Wv, lnw, lnb, rpr);

    dim3 g2(188, HH, BB);
    attn_kernel<<<g2, 256, SMEM_ATTN>>>(out);

    dim3 g3(188, BB);
    fc_kernel<<<g3, 256>>>(x, Wfc, out);

    finalize_kernel<<<24, 256>>>(out);
}